// round 10
// baseline (speedup 1.0000x reference)
#include <cuda_runtime.h>
#include <cstdint>

// ---------------------------------------------------------------------------
// Problem constants (fixed shapes per reference)
// ---------------------------------------------------------------------------
#define TOKENS   4096          // B*N = 2*2048
#define NB       2048          // N (sequence length per batch)
#define DMODEL   768
#define NEXP     8
#define FDIM     3072
#define MAXA     8192          // max assignments per expert (hard upper bound)
#define V_MAX_C  3.0f
#define FCLAMP   10.0f

// ---------------------------------------------------------------------------
// Device scratch (allocation-free rule: __device__ globals)
// ---------------------------------------------------------------------------
__device__ float g_areal[TOKENS];
__device__ float g_dr[TOKENS], g_di[TOKENS];
__device__ float g_er[TOKENS], g_ei[TOKENS];
__device__ float g_fr[TOKENS], g_fi[TOKENS];
__device__ int   g_counts[NEXP];
__device__ int   g_list[NEXP * MAXA];
__device__ float g_cw[2 * TOKENS];                      // combine weight per assignment
__device__ float g_H[(size_t)2 * TOKENS * FDIM];        // GEMM1 output (gelu'd)   ~100.7 MB
__device__ float g_Y[(size_t)2 * TOKENS * DMODEL];      // GEMM2 output (scaled)   ~25.2 MB

// ---------------------------------------------------------------------------
// Kernel 0: zero the expert counters
// ---------------------------------------------------------------------------
__global__ void init_kernel() {
    if (threadIdx.x < NEXP) g_counts[threadIdx.x] = 0;
}

// ---------------------------------------------------------------------------
// Kernel 1: routing + potential projection
// One block per token, 256 threads. 8 warps compute the 8 gate logits;
// warp 0 additionally computes the v-projection.
// ---------------------------------------------------------------------------
__global__ __launch_bounds__(256)
void route_kernel(const float* __restrict__ x,
                  const float* __restrict__ v_w,
                  const float* __restrict__ v_b,
                  const float* __restrict__ gate_w,
                  const float* __restrict__ gate_b)
{
    __shared__ float xs[DMODEL];
    __shared__ float lg[NEXP];
    __shared__ float vsh;

    const int t = blockIdx.x;
    const float* xr = x + (size_t)t * DMODEL;
    for (int i = threadIdx.x; i < DMODEL; i += 256) xs[i] = xr[i];
    __syncthreads();

    const int w = threadIdx.x >> 5;
    const int lane = threadIdx.x & 31;

    float acc = 0.f;
    for (int d = lane; d < DMODEL; d += 32) acc += xs[d] * gate_w[d * NEXP + w];
    #pragma unroll
    for (int o = 16; o; o >>= 1) acc += __shfl_down_sync(0xffffffffu, acc, o);
    if (lane == 0) lg[w] = acc + gate_b[w];

    if (w == 0) {
        float va = 0.f;
        for (int d = lane; d < DMODEL; d += 32) va += xs[d] * v_w[d];
        #pragma unroll
        for (int o = 16; o; o >>= 1) va += __shfl_down_sync(0xffffffffu, va, o);
        if (lane == 0) vsh = va;
    }
    __syncthreads();

    if (threadIdx.x == 0) {
        float v = vsh + v_b[0];
        v = fminf(fmaxf(v, -V_MAX_C), V_MAX_C);
        g_areal[t] = -2.0f + v;

        float b0 = -1e30f, b1 = -1e30f;
        int i0 = 0, i1 = 0;
        #pragma unroll
        for (int e = 0; e < NEXP; e++) {
            float l = lg[e];
            if (l > b0)      { b1 = b0; i1 = i0; b0 = l; i0 = e; }
            else if (l > b1) { b1 = l;  i1 = e; }
        }
        // normalized top-2 softmax weights: p0/(p0+p1) = 1/(1+exp(l1-l0))
        float w0 = 1.0f / (1.0f + expf(b1 - b0));
        float w1 = 1.0f - w0;
        g_cw[2 * t + 0] = w0;
        g_cw[2 * t + 1] = w1;
        int s0 = atomicAdd(&g_counts[i0], 1);
        g_list[i0 * MAXA + s0] = 2 * t + 0;
        int s1 = atomicAdd(&g_counts[i1], 1);
        g_list[i1 * MAXA + s1] = 2 * t + 1;
    }
}

// ---------------------------------------------------------------------------
// Kernel 2: BK Green's function (4 serial continued-fraction chains) + feats
// Single block, 128 threads. Threads 0..3 run the chains (uniform control
// flow: direction folded into index arithmetic so the warp stays converged).
// ---------------------------------------------------------------------------
__global__ void scan_kernel()
{
    const int tid = threadIdx.x;
    if (tid < 4) {
        const int b = tid >> 1;
        const bool fwd = (tid & 1) == 0;
        const int base = b * NB;
        int idx = fwd ? base : base + NB - 1;
        const int stp = fwd ? 1 : -1;
        float* R = fwd ? g_dr : g_er;
        float* I = fwd ? g_di : g_ei;

        float dr = g_areal[idx], di = -1.0f;
        R[idx] = dr; I[idx] = di;
        for (int s = 1; s < NB; s++) {
            idx += stp;
            float inv = __fdividef(1.0f, fmaf(dr, dr, di * di));
            float ndr = g_areal[idx] - dr * inv;   // a_r - Re(1/d)
            float ndi = -1.0f + di * inv;          // a_i - Im(1/d) = -1 + y*inv
            dr = ndr; di = ndi;
            R[idx] = dr; I[idx] = di;
        }
    }
    __syncthreads();

    for (int t = tid; t < TOKENS; t += blockDim.x) {
        float sr = g_dr[t] + g_er[t] - g_areal[t];
        float si = g_di[t] + g_ei[t] + 1.0f;       // - (-1)
        float inv = __fdividef(1.0f, fmaf(sr, sr, si * si));
        float gr = sr * inv;
        float gi = -si * inv;
        g_fr[t] = fminf(fmaxf(gr, -FCLAMP), FCLAMP);
        g_fi[t] = fminf(fmaxf(gi, -FCLAMP), FCLAMP);
    }
}

// ---------------------------------------------------------------------------
// Kernels 3 & 4: grouped per-expert GEMMs.
// 128x128x8 tiling, 256 threads, 8x8 micro-tile, fp32.
// Grid: (MAXA/128, NTOT/128, NEXP); blocks past count[e] exit immediately.
// Stage1 (SHIFT,GELU):   H[a] = gelu(x[a>>1] @ w1[e] + b1[e])
// Stage2 (SCALE):        Y[a] = cw[a] * (H[a] @ w2[e] + b2[e])
// ---------------------------------------------------------------------------
template<int KTOT, int LDA, int NTOT, bool SHIFT, bool DO_GELU, bool DO_SCALE>
__global__ __launch_bounds__(256)
void moe_gemm(const float* __restrict__ Asrc,
              const float* __restrict__ Bsrc,
              const float* __restrict__ bias)
{
    constexpr int BM = 128, BN = 128, BK = 8;
    __shared__ float As[BK][BM];
    __shared__ float Bs[BK][BN];
    __shared__ int   rowId[BM];

    const int e = blockIdx.z;
    const int cnt = g_counts[e];
    const int m0 = blockIdx.x * BM;
    if (m0 >= cnt) return;
    const int n0 = blockIdx.y * BN;
    const int tid = threadIdx.x;

    if (tid < BM) {
        int idx = m0 + tid;
        rowId[tid] = (idx < cnt) ? g_list[e * MAXA + idx] : -1;
    }
    __syncthreads();

    const float* Abase = SHIFT ? Asrc : (const float*)g_H;
    float* Out = DO_GELU ? (float*)g_H : (float*)g_Y;

    // A-tile loader: thread -> (row = tid/2, 4 consecutive k at (tid&1)*4)
    const int am = tid >> 1;
    const int ak = (tid & 1) * 4;
    const int aid_l = rowId[am];
    const float* Ap = nullptr;
    if (aid_l >= 0) {
        int r = SHIFT ? (aid_l >> 1) : aid_l;
        Ap = Abase + (size_t)r * LDA + ak;
    }
    // B-tile loader: thread -> (k = tid/32, 4 consecutive n at (tid&31)*4)
    const int bk_ = tid >> 5;
    const int bn_ = (tid & 31) * 4;
    const float* Bl = Bsrc + (size_t)e * KTOT * NTOT + (size_t)bk_ * NTOT + n0 + bn_;
    const float* biasp = bias + (size_t)e * NTOT + n0;

    float acc[8][8];
    #pragma unroll
    for (int i = 0; i < 8; i++)
        #pragma unroll
        for (int j = 0; j < 8; j++) acc[i][j] = 0.f;

    const int ty = tid >> 4;
    const int tx = tid & 15;

    for (int k0 = 0; k0 < KTOT; k0 += BK) {
        float4 av = Ap ? *(const float4*)(Ap + k0) : make_float4(0.f, 0.f, 0.f, 0.f);
        float4 bv = *(const float4*)Bl;
        Bl += (size_t)BK * NTOT;

        As[ak + 0][am] = av.x;
        As[ak + 1][am] = av.y;
        As[ak + 2][am] = av.z;
        As[ak + 3][am] = av.w;
        *(float4*)&Bs[bk_][bn_] = bv;
        __syncthreads();

        #pragma unroll
        for (int kk = 0; kk < BK; kk++) {
            float a[8], b[8];
            *(float4*)&a[0] = *(const float4*)&As[kk][ty * 8];
            *(float4*)&a[4] = *(const float4*)&As[kk][ty * 8 + 4];
            *(float4*)&b[0] = *(const float4*)&Bs[kk][tx * 8];
            *(float4*)&b[4] = *(const float4*)&Bs[kk][tx * 8 + 4];
            #pragma unroll
            for (int i = 0; i < 8; i++)
                #pragma unroll
                for (int j = 0; j < 8; j++)
                    acc[i][j] = fmaf(a[i], b[j], acc[i][j]);
        }
        __syncthreads();
    }

    // epilogue
    #pragma unroll
    for (int i = 0; i < 8; i++) {
        int aid = rowId[ty * 8 + i];
        if (aid < 0) continue;
        float sc = DO_SCALE ? g_cw[aid] : 1.0f;
        float* op = Out + (size_t)aid * NTOT + n0 + tx * 8;
        float vals[8];
        #pragma unroll
        for (int j = 0; j < 8; j++) {
            float v = acc[i][j] + biasp[tx * 8 + j];
            if (DO_GELU) {
                // jax.nn.gelu (approximate=True, tanh form)
                float c = v * (1.0f + 0.044715f * v * v);
                v = 0.5f * v * (1.0f + tanhf(0.7978845608028654f * c));
            }
            if (DO_SCALE) v *= sc;
            vals[j] = v;
        }
        *(float4*)op       = *(float4*)&vals[0];
        *(float4*)(op + 4) = *(float4*)&vals[4];
    }
}

// ---------------------------------------------------------------------------
// Kernel 5: combine FFN contributions with the spectral branch
// out[t,d] = Y[2t,d] + Y[2t+1,d] + bk[d]*(fr*ow0[d] + fi*ow1[d] + ob[d])
// ---------------------------------------------------------------------------
__global__ __launch_bounds__(256)
void combine_kernel(const float* __restrict__ out_w,
                    const float* __restrict__ out_b,
                    const float* __restrict__ bk_scale,
                    float* __restrict__ out)
{
    const int t = blockIdx.x;
    const float fr = g_fr[t];
    const float fi = g_fi[t];
    const float* y0 = g_Y + (size_t)(2 * t)     * DMODEL;
    const float* y1 = g_Y + (size_t)(2 * t + 1) * DMODEL;
    float* o = out + (size_t)t * DMODEL;
    for (int d = threadIdx.x; d < DMODEL; d += 256) {
        float spec = fr * out_w[d] + fi * out_w[DMODEL + d] + out_b[d];
        o[d] = y0[d] + y1[d] + bk_scale[d] * spec;
    }
}

// ---------------------------------------------------------------------------
// Launch
// ---------------------------------------------------------------------------
extern "C" void kernel_launch(void* const* d_in, const int* in_sizes, int n_in,
                              void* d_out, int out_size)
{
    const float* x        = (const float*)d_in[0];   // (B,N,D)
    const float* v_w      = (const float*)d_in[1];   // (D,)
    const float* v_b      = (const float*)d_in[2];   // scalar
    const float* gate_w   = (const float*)d_in[3];   // (D,E)
    const float* gate_b   = (const float*)d_in[4];   // (E,)
    const float* w1       = (const float*)d_in[5];   // (E,D,F)
    const float* b1       = (const float*)d_in[6];   // (E,F)
    const float* w2       = (const float*)d_in[7];   // (E,F,D)
    const float* b2       = (const float*)d_in[8];   // (E,D)
    const float* out_w    = (const float*)d_in[9];   // (2,D)
    const float* out_b    = (const float*)d_in[10];  // (D,)
    const float* bk_scale = (const float*)d_in[11];  // (D,)
    float* out = (float*)d_out;

    init_kernel<<<1, 32>>>();
    route_kernel<<<TOKENS, 256>>>(x, v_w, v_b, gate_w, gate_b);
    scan_kernel<<<1, 128>>>();

    // GEMM1: H = gelu(X_gathered @ W1[e] + b1[e]),  K=768, N=3072
    {
        dim3 grid(MAXA / 128, FDIM / 128, NEXP);
        moe_gemm<DMODEL, DMODEL, FDIM, true, true, false><<<grid, 256>>>(x, w1, b1);
    }
    // GEMM2: Y = cw * (H @ W2[e] + b2[e]),  K=3072, N=768
    {
        dim3 grid(MAXA / 128, DMODEL / 128, NEXP);
        moe_gemm<FDIM, FDIM, DMODEL, false, false, true><<<grid, 256>>>(nullptr, w2, b2);
    }

    combine_kernel<<<TOKENS, 256>>>(out_w, out_b, bk_scale, out);
}

// round 11
// speedup vs baseline: 1.0024x; 1.0024x over previous
#include <cuda_runtime.h>
#include <cstdint>

// ---------------------------------------------------------------------------
// Problem constants (fixed shapes per reference)
// ---------------------------------------------------------------------------
#define TOKENS   4096          // B*N = 2*2048
#define NB       2048          // N (sequence length per batch)
#define DMODEL   768
#define NEXP     8
#define FDIM     3072
#define MAXA     8192          // max assignments per expert (hard upper bound)
#define V_MAX_C  3.0f
#define FCLAMP   10.0f

// ---------------------------------------------------------------------------
// Device scratch (allocation-free rule: __device__ globals)
// ---------------------------------------------------------------------------
__device__ float g_areal[TOKENS];
__device__ float g_dr[TOKENS], g_di[TOKENS];
__device__ float g_er[TOKENS], g_ei[TOKENS];
__device__ float g_fr[TOKENS], g_fi[TOKENS];
__device__ int   g_counts[NEXP];
__device__ int   g_list[NEXP * MAXA];
__device__ float g_cw[2 * TOKENS];                      // combine weight per assignment
__device__ float g_H[(size_t)2 * TOKENS * FDIM];        // GEMM1 output (gelu'd)   ~100.7 MB
__device__ float g_Y[(size_t)2 * TOKENS * DMODEL];      // GEMM2 output (scaled)   ~25.2 MB

// ---------------------------------------------------------------------------
// Kernel 0: zero the expert counters
// ---------------------------------------------------------------------------
__global__ void init_kernel() {
    if (threadIdx.x < NEXP) g_counts[threadIdx.x] = 0;
}

// ---------------------------------------------------------------------------
// Kernel 1: routing + potential projection
// One block per token, 256 threads. 8 warps compute the 8 gate logits;
// warp 0 additionally computes the v-projection.
// ---------------------------------------------------------------------------
__global__ __launch_bounds__(256)
void route_kernel(const float* __restrict__ x,
                  const float* __restrict__ v_w,
                  const float* __restrict__ v_b,
                  const float* __restrict__ gate_w,
                  const float* __restrict__ gate_b)
{
    __shared__ float xs[DMODEL];
    __shared__ float lg[NEXP];
    __shared__ float vsh;

    const int t = blockIdx.x;
    const float* xr = x + (size_t)t * DMODEL;
    for (int i = threadIdx.x; i < DMODEL; i += 256) xs[i] = xr[i];
    __syncthreads();

    const int w = threadIdx.x >> 5;
    const int lane = threadIdx.x & 31;

    float acc = 0.f;
    for (int d = lane; d < DMODEL; d += 32) acc += xs[d] * gate_w[d * NEXP + w];
    #pragma unroll
    for (int o = 16; o; o >>= 1) acc += __shfl_down_sync(0xffffffffu, acc, o);
    if (lane == 0) lg[w] = acc + gate_b[w];

    if (w == 0) {
        float va = 0.f;
        for (int d = lane; d < DMODEL; d += 32) va += xs[d] * v_w[d];
        #pragma unroll
        for (int o = 16; o; o >>= 1) va += __shfl_down_sync(0xffffffffu, va, o);
        if (lane == 0) vsh = va;
    }
    __syncthreads();

    if (threadIdx.x == 0) {
        float v = vsh + v_b[0];
        v = fminf(fmaxf(v, -V_MAX_C), V_MAX_C);
        g_areal[t] = -2.0f + v;

        float b0 = -1e30f, b1 = -1e30f;
        int i0 = 0, i1 = 0;
        #pragma unroll
        for (int e = 0; e < NEXP; e++) {
            float l = lg[e];
            if (l > b0)      { b1 = b0; i1 = i0; b0 = l; i0 = e; }
            else if (l > b1) { b1 = l;  i1 = e; }
        }
        // normalized top-2 softmax weights: p0/(p0+p1) = 1/(1+exp(l1-l0))
        float w0 = 1.0f / (1.0f + expf(b1 - b0));
        float w1 = 1.0f - w0;
        g_cw[2 * t + 0] = w0;
        g_cw[2 * t + 1] = w1;
        int s0 = atomicAdd(&g_counts[i0], 1);
        g_list[i0 * MAXA + s0] = 2 * t + 0;
        int s1 = atomicAdd(&g_counts[i1], 1);
        g_list[i1 * MAXA + s1] = 2 * t + 1;
    }
}

// ---------------------------------------------------------------------------
// Kernel 2: BK Green's function (4 serial continued-fraction chains) + feats
// Single block, 128 threads. Threads 0..3 run the chains (uniform control
// flow: direction folded into index arithmetic so the warp stays converged).
// ---------------------------------------------------------------------------
__global__ void scan_kernel()
{
    const int tid = threadIdx.x;
    if (tid < 4) {
        const int b = tid >> 1;
        const bool fwd = (tid & 1) == 0;
        const int base = b * NB;
        int idx = fwd ? base : base + NB - 1;
        const int stp = fwd ? 1 : -1;
        float* R = fwd ? g_dr : g_er;
        float* I = fwd ? g_di : g_ei;

        float dr = g_areal[idx], di = -1.0f;
        R[idx] = dr; I[idx] = di;
        for (int s = 1; s < NB; s++) {
            idx += stp;
            float inv = __fdividef(1.0f, fmaf(dr, dr, di * di));
            float ndr = g_areal[idx] - dr * inv;   // a_r - Re(1/d)
            float ndi = -1.0f + di * inv;          // a_i - Im(1/d) = -1 + y*inv
            dr = ndr; di = ndi;
            R[idx] = dr; I[idx] = di;
        }
    }
    __syncthreads();

    for (int t = tid; t < TOKENS; t += blockDim.x) {
        float sr = g_dr[t] + g_er[t] - g_areal[t];
        float si = g_di[t] + g_ei[t] + 1.0f;       // - (-1)
        float inv = __fdividef(1.0f, fmaf(sr, sr, si * si));
        float gr = sr * inv;
        float gi = -si * inv;
        g_fr[t] = fminf(fmaxf(gr, -FCLAMP), FCLAMP);
        g_fi[t] = fminf(fmaxf(gi, -FCLAMP), FCLAMP);
    }
}

// ---------------------------------------------------------------------------
// Kernels 3 & 4: grouped per-expert GEMMs.
// 128x128x8 tiling, 256 threads, 8x8 micro-tile, fp32.
// Grid: (MAXA/128, NTOT/128, NEXP); blocks past count[e] exit immediately.
// Stage1 (SHIFT,GELU):   H[a] = gelu(x[a>>1] @ w1[e] + b1[e])
// Stage2 (SCALE):        Y[a] = cw[a] * (H[a] @ w2[e] + b2[e])
// ---------------------------------------------------------------------------
template<int KTOT, int LDA, int NTOT, bool SHIFT, bool DO_GELU, bool DO_SCALE>
__global__ __launch_bounds__(256)
void moe_gemm(const float* __restrict__ Asrc,
              const float* __restrict__ Bsrc,
              const float* __restrict__ bias)
{
    constexpr int BM = 128, BN = 128, BK = 8;
    __shared__ float As[BK][BM];
    __shared__ float Bs[BK][BN];
    __shared__ int   rowId[BM];

    const int e = blockIdx.z;
    const int cnt = g_counts[e];
    const int m0 = blockIdx.x * BM;
    if (m0 >= cnt) return;
    const int n0 = blockIdx.y * BN;
    const int tid = threadIdx.x;

    if (tid < BM) {
        int idx = m0 + tid;
        rowId[tid] = (idx < cnt) ? g_list[e * MAXA + idx] : -1;
    }
    __syncthreads();

    const float* Abase = SHIFT ? Asrc : (const float*)g_H;
    float* Out = DO_GELU ? (float*)g_H : (float*)g_Y;

    // A-tile loader: thread -> (row = tid/2, 4 consecutive k at (tid&1)*4)
    const int am = tid >> 1;
    const int ak = (tid & 1) * 4;
    const int aid_l = rowId[am];
    const float* Ap = nullptr;
    if (aid_l >= 0) {
        int r = SHIFT ? (aid_l >> 1) : aid_l;
        Ap = Abase + (size_t)r * LDA + ak;
    }
    // B-tile loader: thread -> (k = tid/32, 4 consecutive n at (tid&31)*4)
    const int bk_ = tid >> 5;
    const int bn_ = (tid & 31) * 4;
    const float* Bl = Bsrc + (size_t)e * KTOT * NTOT + (size_t)bk_ * NTOT + n0 + bn_;
    const float* biasp = bias + (size_t)e * NTOT + n0;

    float acc[8][8];
    #pragma unroll
    for (int i = 0; i < 8; i++)
        #pragma unroll
        for (int j = 0; j < 8; j++) acc[i][j] = 0.f;

    const int ty = tid >> 4;
    const int tx = tid & 15;

    for (int k0 = 0; k0 < KTOT; k0 += BK) {
        float4 av = Ap ? *(const float4*)(Ap + k0) : make_float4(0.f, 0.f, 0.f, 0.f);
        float4 bv = *(const float4*)Bl;
        Bl += (size_t)BK * NTOT;

        As[ak + 0][am] = av.x;
        As[ak + 1][am] = av.y;
        As[ak + 2][am] = av.z;
        As[ak + 3][am] = av.w;
        *(float4*)&Bs[bk_][bn_] = bv;
        __syncthreads();

        #pragma unroll
        for (int kk = 0; kk < BK; kk++) {
            float a[8], b[8];
            *(float4*)&a[0] = *(const float4*)&As[kk][ty * 8];
            *(float4*)&a[4] = *(const float4*)&As[kk][ty * 8 + 4];
            *(float4*)&b[0] = *(const float4*)&Bs[kk][tx * 8];
            *(float4*)&b[4] = *(const float4*)&Bs[kk][tx * 8 + 4];
            #pragma unroll
            for (int i = 0; i < 8; i++)
                #pragma unroll
                for (int j = 0; j < 8; j++)
                    acc[i][j] = fmaf(a[i], b[j], acc[i][j]);
        }
        __syncthreads();
    }

    // epilogue
    #pragma unroll
    for (int i = 0; i < 8; i++) {
        int aid = rowId[ty * 8 + i];
        if (aid < 0) continue;
        float sc = DO_SCALE ? g_cw[aid] : 1.0f;
        float* op = Out + (size_t)aid * NTOT + n0 + tx * 8;
        float vals[8];
        #pragma unroll
        for (int j = 0; j < 8; j++) {
            float v = acc[i][j] + biasp[tx * 8 + j];
            if (DO_GELU) {
                // jax.nn.gelu (approximate=True, tanh form)
                float c = v * (1.0f + 0.044715f * v * v);
                v = 0.5f * v * (1.0f + tanhf(0.7978845608028654f * c));
            }
            if (DO_SCALE) v *= sc;
            vals[j] = v;
        }
        *(float4*)op       = *(float4*)&vals[0];
        *(float4*)(op + 4) = *(float4*)&vals[4];
    }
}

// ---------------------------------------------------------------------------
// Kernel 5: combine FFN contributions with the spectral branch
// out[t,d] = Y[2t,d] + Y[2t+1,d] + bk[d]*(fr*ow0[d] + fi*ow1[d] + ob[d])
// ---------------------------------------------------------------------------
__global__ __launch_bounds__(256)
void combine_kernel(const float* __restrict__ out_w,
                    const float* __restrict__ out_b,
                    const float* __restrict__ bk_scale,
                    float* __restrict__ out)
{
    const int t = blockIdx.x;
    const float fr = g_fr[t];
    const float fi = g_fi[t];
    const float* y0 = g_Y + (size_t)(2 * t)     * DMODEL;
    const float* y1 = g_Y + (size_t)(2 * t + 1) * DMODEL;
    float* o = out + (size_t)t * DMODEL;
    for (int d = threadIdx.x; d < DMODEL; d += 256) {
        float spec = fr * out_w[d] + fi * out_w[DMODEL + d] + out_b[d];
        o[d] = y0[d] + y1[d] + bk_scale[d] * spec;
    }
}

// ---------------------------------------------------------------------------
// Launch
// ---------------------------------------------------------------------------
extern "C" void kernel_launch(void* const* d_in, const int* in_sizes, int n_in,
                              void* d_out, int out_size)
{
    const float* x        = (const float*)d_in[0];   // (B,N,D)
    const float* v_w      = (const float*)d_in[1];   // (D,)
    const float* v_b      = (const float*)d_in[2];   // scalar
    const float* gate_w   = (const float*)d_in[3];   // (D,E)
    const float* gate_b   = (const float*)d_in[4];   // (E,)
    const float* w1       = (const float*)d_in[5];   // (E,D,F)
    const float* b1       = (const float*)d_in[6];   // (E,F)
    const float* w2       = (const float*)d_in[7];   // (E,F,D)
    const float* b2       = (const float*)d_in[8];   // (E,D)
    const float* out_w    = (const float*)d_in[9];   // (2,D)
    const float* out_b    = (const float*)d_in[10];  // (D,)
    const float* bk_scale = (const float*)d_in[11];  // (D,)
    float* out = (float*)d_out;

    init_kernel<<<1, 32>>>();
    route_kernel<<<TOKENS, 256>>>(x, v_w, v_b, gate_w, gate_b);
    scan_kernel<<<1, 128>>>();

    // GEMM1: H = gelu(X_gathered @ W1[e] + b1[e]),  K=768, N=3072
    {
        dim3 grid(MAXA / 128, FDIM / 128, NEXP);
        moe_gemm<DMODEL, DMODEL, FDIM, true, true, false><<<grid, 256>>>(x, w1, b1);
    }
    // GEMM2: Y = cw * (H @ W2[e] + b2[e]),  K=3072, N=768
    {
        dim3 grid(MAXA / 128, DMODEL / 128, NEXP);
        moe_gemm<FDIM, FDIM, DMODEL, false, false, true><<<grid, 256>>>(nullptr, w2, b2);
    }

    combine_kernel<<<TOKENS, 256>>>(out_w, out_b, bk_scale, out);
}